// round 7
// baseline (speedup 1.0000x reference)
#include <cuda_runtime.h>
#include <cuda_bf16.h>
#include <cstdint>

#define N_NODES 100000
#define EMB_DIM 128
#define HIDDEN  64
#define N_EDGES 1600000
#define TILE_M  128
#define N_TILES ((N_NODES + TILE_M - 1) / TILE_M)   // 782

// Scratch: per-node precomputed [u | v], 128 floats per node (51.2 MB).
__device__ float g_UV[(size_t)N_NODES * 128];
// 1 if edge_index is int64 on device, 0 if int32.
__device__ int g_idx_is_64;

// ---- smem layout for kernel 1 (bf16 tiles, 272B row stride = conflict-free)
#define ROW_BYTES 272                      // 128 bf16 (256B) + 16B pad
#define TILE_BYTES (128 * ROW_BYTES)       // 34816
#define SM_A_HI 0
#define SM_A_LO (SM_A_HI + TILE_BYTES)
#define SM_B_HI (SM_A_LO + TILE_BYTES)
#define SM_B_LO (SM_B_HI + TILE_BYTES)
#define SMEM_TOTAL (4 * TILE_BYTES)        // 139264 B

__device__ __forceinline__ void mma_bf16(float* d, uint32_t a0, uint32_t a1,
                                         uint32_t a2, uint32_t a3,
                                         uint32_t b0, uint32_t b1) {
    asm volatile(
        "mma.sync.aligned.m16n8k16.row.col.f32.bf16.bf16.f32 "
        "{%0,%1,%2,%3}, {%4,%5,%6,%7}, {%8,%9}, {%0,%1,%2,%3};"
        : "+f"(d[0]), "+f"(d[1]), "+f"(d[2]), "+f"(d[3])
        : "r"(a0), "r"(a1), "r"(a2), "r"(a3), "r"(b0), "r"(b1));
}

__device__ __forceinline__ __nv_bfloat162 split_hi(float x0, float x1) {
    __nv_bfloat162 h; h.x = __float2bfloat16(x0); h.y = __float2bfloat16(x1);
    return h;
}
__device__ __forceinline__ __nv_bfloat162 split_lo(float x0, float x1,
                                                   __nv_bfloat162 h) {
    __nv_bfloat162 l;
    l.x = __float2bfloat16(x0 - __bfloat162float(h.x));
    l.y = __float2bfloat16(x1 - __bfloat162float(h.y));
    return l;
}

// ---------------------------------------------------------------------------
// Kernel 1 (warp-MMA): per 128-node tile, UV[m][n] = sum_k emb[m][k]*Wc[k][n]
//   Wc[k][n] = W1[k][n] (n<64) | W1[128+k][n-64] (n>=64)
// Split-bf16 3 passes: Ahi*Bhi + Ahi*Blo + Alo*Bhi, fp32 register accums.
// 8 warps; warp w computes rows [16w,16w+16) x all 128 cols.
// B staged transposed: Wt[n][k] = Wc[k][n] (k contiguous, "col" operand).
// Block 0 additionally detects edge_index dtype.
// ---------------------------------------------------------------------------
__global__ __launch_bounds__(256)
void precompute_uv_mma(const float* __restrict__ emb,
                       const float* __restrict__ W1,
                       const int* __restrict__ eidx32) {
    extern __shared__ char smem[];
    int tid = threadIdx.x;

    // --- dtype detection (block 0): int64 indices < 2^31 have zero odd words
    __shared__ int s_any;
    if (blockIdx.x == 0) {
        if (tid == 0) s_any = 0;
        __syncthreads();
        if (tid < 128) {
            int w = eidx32[2 * (tid * 37 + 1) + 1];
            if (w != 0) atomicOr(&s_any, 1);
        }
        __syncthreads();
        if (tid == 0) g_idx_is_64 = (s_any == 0) ? 1 : 0;
    }

    int base = blockIdx.x * TILE_M;

    // --- stage A (emb tile) hi/lo: row-major, ROW_BYTES stride
    for (int i = tid; i < 128 * 64; i += 256) {
        int row = i >> 6;
        int kk = (i & 63) * 2;
        int node = base + row;
        float2 x = (node < N_NODES)
                 ? *(const float2*)(emb + (size_t)node * EMB_DIM + kk)
                 : make_float2(0.f, 0.f);
        __nv_bfloat162 h = split_hi(x.x, x.y);
        __nv_bfloat162 l = split_lo(x.x, x.y, h);
        *(__nv_bfloat162*)(smem + SM_A_HI + row * ROW_BYTES + kk * 2) = h;
        *(__nv_bfloat162*)(smem + SM_A_LO + row * ROW_BYTES + kk * 2) = l;
    }

    // --- stage B transposed hi/lo: Wt[n][k] = Wc[k][n]
    for (int i = tid; i < 128 * 64; i += 256) {
        int n = i >> 6;
        int kk = (i & 63) * 2;
        float x0, x1;
        if (n < 64) { x0 = W1[kk * 64 + n];         x1 = W1[(kk + 1) * 64 + n]; }
        else        { x0 = W1[(128 + kk) * 64 + n - 64];
                      x1 = W1[(129 + kk) * 64 + n - 64]; }
        __nv_bfloat162 h = split_hi(x0, x1);
        __nv_bfloat162 l = split_lo(x0, x1, h);
        *(__nv_bfloat162*)(smem + SM_B_HI + n * ROW_BYTES + kk * 2) = h;
        *(__nv_bfloat162*)(smem + SM_B_LO + n * ROW_BYTES + kk * 2) = l;
    }
    __syncthreads();

    int wid = tid >> 5, lane = tid & 31;
    int g = lane >> 2, t = lane & 3;
    int m0 = wid * 16;

    float acc[16][4];
    #pragma unroll
    for (int j = 0; j < 16; j++)
        acc[j][0] = acc[j][1] = acc[j][2] = acc[j][3] = 0.f;

    const int a_sel[3] = {SM_A_HI, SM_A_HI, SM_A_LO};
    const int b_sel[3] = {SM_B_HI, SM_B_LO, SM_B_HI};

    for (int p = 0; p < 3; p++) {
        const char* Ab = smem + a_sel[p];
        const char* Bb = smem + b_sel[p];
        for (int ks = 0; ks < 8; ks++) {
            int k0 = ks * 16;
            // A fragment (m16 x k16):
            //   a0={A[g][2t],A[g][2t+1]}  a1={A[g+8][2t],..}
            //   a2={A[g][2t+8],..}        a3={A[g+8][2t+8],..}
            uint32_t a0 = *(const uint32_t*)(Ab + (m0 + g)     * ROW_BYTES + (k0 + 2 * t)     * 2);
            uint32_t a1 = *(const uint32_t*)(Ab + (m0 + 8 + g) * ROW_BYTES + (k0 + 2 * t)     * 2);
            uint32_t a2 = *(const uint32_t*)(Ab + (m0 + g)     * ROW_BYTES + (k0 + 2 * t + 8) * 2);
            uint32_t a3 = *(const uint32_t*)(Ab + (m0 + 8 + g) * ROW_BYTES + (k0 + 2 * t + 8) * 2);
            #pragma unroll
            for (int j = 0; j < 16; j++) {
                // B fragment (k16 x n8): b0={B[2t][g],B[2t+1][g]}, b1={B[2t+8][g],..}
                // stored as Wt[n][k] row-major -> contiguous along k
                uint32_t b0 = *(const uint32_t*)(Bb + (8 * j + g) * ROW_BYTES + (k0 + 2 * t)     * 2);
                uint32_t b1 = *(const uint32_t*)(Bb + (8 * j + g) * ROW_BYTES + (k0 + 2 * t + 8) * 2);
                mma_bf16(acc[j], a0, a1, a2, a3, b0, b1);
            }
        }
    }

    // --- write out: lane owns D[g][2t..2t+1] and D[g+8][2t..2t+1] per n-tile
    int node0 = base + m0 + g;
    int node1 = base + m0 + 8 + g;
    #pragma unroll
    for (int j = 0; j < 16; j++) {
        int col = 8 * j + 2 * t;
        if (node0 < N_NODES)
            *(float2*)(g_UV + (size_t)node0 * 128 + col) = make_float2(acc[j][0], acc[j][1]);
        if (node1 < N_NODES)
            *(float2*)(g_UV + (size_t)node1 * 128 + col) = make_float2(acc[j][2], acc[j][3]);
    }
}

// ---------------------------------------------------------------------------
// Kernel 2: per-edge score (unchanged R5 winner).
// 8 lanes per edge; lane s owns cols {4s..4s+3, 32+4s..32+4s+3} so every
// LDG.128's 8-lane group covers exactly one contiguous 128B line.
// ---------------------------------------------------------------------------
__global__ __launch_bounds__(256)
void edge_score_kernel(const void* __restrict__ eidx_raw,
                       const float* __restrict__ b1,
                       const float* __restrict__ W2,
                       const float* __restrict__ b2,
                       float* __restrict__ out) {
    __shared__ float sb1[64];
    __shared__ float sw2[64];
    __shared__ float sb2;
    if (threadIdx.x < 64) {
        sb1[threadIdx.x] = b1[threadIdx.x];
        sw2[threadIdx.x] = W2[threadIdx.x];
    }
    if (threadIdx.x == 0) sb2 = b2[0];
    __syncthreads();

    int gtid = blockIdx.x * blockDim.x + threadIdx.x;
    int e = gtid >> 3;
    if (e >= N_EDGES) return;
    int s = threadIdx.x & 7;

    long long src, tgt;
    if (g_idx_is_64) {
        const long long* eidx = (const long long*)eidx_raw;
        src = eidx[e];
        tgt = eidx[N_EDGES + e];
    } else {
        const int* eidx = (const int*)eidx_raw;
        src = eidx[e];
        tgt = eidx[N_EDGES + e];
    }

    const float4* urow = (const float4*)(g_UV + (size_t)src * 128);
    const float4* vrow = (const float4*)(g_UV + (size_t)tgt * 128) + 16;
    float4 u0 = urow[s];
    float4 u1 = urow[8 + s];
    float4 v0 = vrow[s];
    float4 v1 = vrow[8 + s];

    float4 bb0 = *(const float4*)(sb1 + s * 4);
    float4 bb1 = *(const float4*)(sb1 + 32 + s * 4);
    float4 w0  = *(const float4*)(sw2 + s * 4);
    float4 w1  = *(const float4*)(sw2 + 32 + s * 4);

    float p = 0.f;
    {
        float z;
        z = fmaxf(u0.x + v0.x + bb0.x, 0.f); p = fmaf(z, w0.x, p);
        z = fmaxf(u0.y + v0.y + bb0.y, 0.f); p = fmaf(z, w0.y, p);
        z = fmaxf(u0.z + v0.z + bb0.z, 0.f); p = fmaf(z, w0.z, p);
        z = fmaxf(u0.w + v0.w + bb0.w, 0.f); p = fmaf(z, w0.w, p);
        z = fmaxf(u1.x + v1.x + bb1.x, 0.f); p = fmaf(z, w1.x, p);
        z = fmaxf(u1.y + v1.y + bb1.y, 0.f); p = fmaf(z, w1.y, p);
        z = fmaxf(u1.z + v1.z + bb1.z, 0.f); p = fmaf(z, w1.z, p);
        z = fmaxf(u1.w + v1.w + bb1.w, 0.f); p = fmaf(z, w1.w, p);
    }

    p += __shfl_xor_sync(0xFFFFFFFFu, p, 4);
    p += __shfl_xor_sync(0xFFFFFFFFu, p, 2);
    p += __shfl_xor_sync(0xFFFFFFFFu, p, 1);

    if (s == 0) out[e] = p + sb2;
}

// ---------------------------------------------------------------------------
extern "C" void kernel_launch(void* const* d_in, const int* in_sizes, int n_in,
                              void* d_out, int out_size) {
    const float* emb  = (const float*)d_in[0];
    const void*  eidx = d_in[1];
    const float* W1   = (const float*)d_in[2];
    const float* b1   = (const float*)d_in[3];
    const float* W2   = (const float*)d_in[4];
    const float* b2   = (const float*)d_in[5];
    float*       out  = (float*)d_out;

    cudaFuncSetAttribute(precompute_uv_mma,
                         cudaFuncAttributeMaxDynamicSharedMemorySize, SMEM_TOTAL);

    // Kernel 1: 782 CTAs, one 128-node tile each (block 0 also detects dtype)
    precompute_uv_mma<<<N_TILES, 256, SMEM_TOTAL>>>(emb, W1, (const int*)eidx);

    // Kernel 2: 8 threads per edge
    {
        long long threads = (long long)N_EDGES * 8;
        int blocks = (int)((threads + 255) / 256);
        edge_score_kernel<<<blocks, 256>>>(eidx, b1, W2, b2, out);
    }
}